// round 17
// baseline (speedup 1.0000x reference)
#include <cuda_runtime.h>

#define T_STEPS 500
#define N_NEUR  20000
#define NGRP    313              // blocks of 128 thr, 64 neurons each
#define DT      0.1f
#define UNROLL  10               // 500 = 10 * 50
#define NBLK    (T_STEPS / UNROLL)

__device__ __forceinline__ float fast_tanh(float t) {
    float r;
    asm("tanh.approx.f32 %0, %1;" : "=f"(r) : "f"(t));
    return r;
}

__global__ void __launch_bounds__(128, 8) hh_kernel(
    const float* __restrict__ i_inj,   // [T, N]
    const float* __restrict__ x0,      // [7, N]
    const float* __restrict__ params,  // [28]
    float* __restrict__ out)           // [T, 7, N]
{
    // Functional split: per 32 neurons, warp A (wid 0,2) integrates V,cac,h,e,f;
    // warp B (wid 1,3) integrates p,q,n and the i_kf product w = gKf*p^4*q.
    // Coupling via SMEM: A posts V (bar1); B posts {w, n} (bar2).
    __shared__ float Vsh[64], wsh[64], nsh[64];

    const int tid  = threadIdx.x;
    const int wid  = tid >> 5;
    const int lane = tid & 31;
    const int half = wid >> 1;            // pair 0 / 1 within block
    const bool isA = (wid & 1) == 0;      // A on SMSP 0,2 ; B on SMSP 1,3
    const int sidx = half * 32 + lane;

    int n = blockIdx.x * 64 + half * 32 + lane;
    const bool act = (n < N_NEUR);
    if (!act) n = N_NEUR - 1;             // clamp for loads; stores guarded

    // ---- fold constants
    const float decay_ca = params[0];
    const float rho_ca   = params[1];
    const float p_tau = params[2],  p_scale = params[3],  p_mdp = params[4];
    const float q_tau = params[5],  q_scale = params[6],  q_mdp = params[7];
    const float n_tau = params[8],  n_scale = params[9],  n_mdp = params[10];
    const float f_tau = params[11], f_scale = params[12], f_mdp = params[13];
    const float e_tau = params[14], e_scale = params[15], e_mdp = params[16];
    const float h_alpha = params[17], h_scale = params[18], h_mdp = params[19];
    const float C_m = params[20], g_Ca = params[21], g_Ks = params[22];
    const float g_Kf = params[23], g_L = params[24];
    const float E_Ca = params[25], E_K = params[26], E_L = params[27];

    const float pc1 = 0.5f / p_scale, pc0 = -p_mdp * 0.5f / p_scale;
    const float qc1 = 0.5f / q_scale, qc0 = -q_mdp * 0.5f / q_scale;
    const float nc1 = 0.5f / n_scale, nc0 = -n_mdp * 0.5f / n_scale;
    const float fc1 = 0.5f / f_scale, fc0 = -f_mdp * 0.5f / f_scale;
    const float ec1 = 0.5f / e_scale, ec0 = -e_mdp * 0.5f / e_scale;
    const float hc1 = 0.5f / h_scale, hc0 = -h_mdp * 0.5f / h_scale;

    const float Ap = p_tau / (p_tau + DT), Bp = 0.5f * DT / (p_tau + DT);
    const float Aq = q_tau / (q_tau + DT), Bq = 0.5f * DT / (q_tau + DT);
    const float An = n_tau / (n_tau + DT), Bn = 0.5f * DT / (n_tau + DT);
    const float Af = f_tau / (f_tau + DT), Bf = 0.5f * DT / (f_tau + DT);
    const float Ae = e_tau / (e_tau + DT), Be = 0.5f * DT / (e_tau + DT);

    const float hb = 0.5f * h_alpha, ha = 1.0f - 0.5f * h_alpha;
    const float dtCm  = DT / C_m;
    const float cdec  = 1.0f - DT / decay_ca;
    const float rhoDt = rho_ca * DT;

    float* o = out + n;
    const float* inj = i_inj + n;

    // ---- role state init
    float V = 0.f, e = 0.f, f = 0.f, cac = 0.f, gef = 0.f;   // A
    float wr = 0.f, nr = 0.f;                                 // A: from B
    float p = 0.f, q = 0.f, nn = 0.f;                         // B
    float cur[UNROLL];

    if (isA) {
        V   = x0[0 * N_NEUR + n];
        e   = x0[4 * N_NEUR + n];
        f   = x0[5 * N_NEUR + n];
        cac = x0[6 * N_NEUR + n];
        // bootstrap B-products at t=0 (same association as B's formula)
        const float p0 = x0[1 * N_NEUR + n];
        const float q0 = x0[2 * N_NEUR + n];
        nr = x0[3 * N_NEUR + n];
        const float p2 = p0 * p0, p4 = p2 * p2;
        wr = g_Kf * (p4 * q0);
        // h_0 and gef_0
        const float h = fmaf(hb, fast_tanh(fmaf(cac, hc1, hc0)), ha);
        gef = g_Ca * e * e * f * h;
        #pragma unroll
        for (int u = 0; u < UNROLL; ++u)
            cur[u] = __ldcs(inj + u * N_NEUR);
        inj += UNROLL * N_NEUR;
    } else {
        p  = x0[1 * N_NEUR + n];
        q  = x0[2 * N_NEUR + n];
        nn = x0[3 * N_NEUR + n];
    }

    #pragma unroll 1
    for (int blk = 0; blk < NBLK; ++blk) {
        float nxt[UNROLL];
        if (isA && blk < NBLK - 1) {
            #pragma unroll
            for (int u = 0; u < UNROLL; ++u)
                nxt[u] = __ldcs(inj + u * N_NEUR);
            inj += UNROLL * N_NEUR;
        }

        #pragma unroll
        for (int u = 0; u < UNROLL; ++u) {
            float i_ca = 0.f, dV = 0.f;
            if (isA) {
                const float icur = cur[u];
                i_ca = gef * (V - E_Ca);
                const float VmEK = V - E_K;
                const float i_ks = g_Ks * nr * VmEK;
                const float i_kf = wr * VmEK;          // w already has gKf folded
                const float i_l  = g_L * (V - E_L);
                const float itot = icur - ((i_ca + i_ks) + (i_kf + i_l));
                dV = itot * dtCm;
                V += dV;
                Vsh[sidx] = V;                          // publish V_{t+1}
            }
            __syncthreads();                            // bar1: V ready

            if (isA) {
                // cac with updated V via identity, then h_{t+1}, e,f gates, gef
                const float i_ca2 = fmaf(gef, dV, i_ca);
                cac = fmaf(cac, cdec, -i_ca2 * rhoDt);
                const float h = fmaf(hb, fast_tanh(fmaf(cac, hc1, hc0)), ha);
                e = fmaf(Be, fast_tanh(fmaf(V, ec1, ec0)), fmaf(Ae, e, Be));
                f = fmaf(Bf, fast_tanh(fmaf(V, fc1, fc0)), fmaf(Af, f, Bf));
                gef = g_Ca * e * e * f * h;
                if (act) {
                    __stcs(o + 0 * N_NEUR, V);
                    __stcs(o + 4 * N_NEUR, e);
                    __stcs(o + 5 * N_NEUR, f);
                    __stcs(o + 6 * N_NEUR, cac);
                }
            } else {
                const float Vn = Vsh[sidx];
                p  = fmaf(Bp, fast_tanh(fmaf(Vn, pc1, pc0)), fmaf(Ap, p,  Bp));
                q  = fmaf(Bq, fast_tanh(fmaf(Vn, qc1, qc0)), fmaf(Aq, q,  Bq));
                nn = fmaf(Bn, fast_tanh(fmaf(Vn, nc1, nc0)), fmaf(An, nn, Bn));
                const float p2 = p * p, p4 = p2 * p2;
                wsh[sidx] = g_Kf * (p4 * q);
                nsh[sidx] = nn;
                if (act) {
                    __stcs(o + 1 * N_NEUR, p);
                    __stcs(o + 2 * N_NEUR, q);
                    __stcs(o + 3 * N_NEUR, nn);
                }
            }
            __syncthreads();                            // bar2: w,n ready

            if (isA) {
                wr = wsh[sidx];                         // LDS early for next step
                nr = nsh[sidx];
            }
            o += 7 * N_NEUR;
        }

        if (isA) {
            #pragma unroll
            for (int u = 0; u < UNROLL; ++u)
                cur[u] = nxt[u];
        }
    }
}

extern "C" void kernel_launch(void* const* d_in, const int* in_sizes, int n_in,
                              void* d_out, int out_size) {
    const float* i_inj  = (const float*)d_in[0];
    const float* x0     = (const float*)d_in[1];
    const float* params = (const float*)d_in[2];
    float* out = (float*)d_out;

    // 313 blocks x 128 thr: 2 A/B pairs per block, 64 neurons/block,
    // zero duplicated compute; ~62 (vs 106) warp-instrs per SMSP-step.
    hh_kernel<<<NGRP, 128>>>(i_inj, x0, params, out);
}